// round 4
// baseline (speedup 1.0000x reference)
#include <cuda_runtime.h>
#include <cuda_bf16.h>

#define HIDDEN   1024
#define CODEBOOK 8192
#define NTOK     8192
#define BM 64
#define BN 64
#define BK 16
#define SMPAD 68          // padded row stride for [BK][*] tiles (272B, 16B-aligned)
#define NCHUNK (HIDDEN / BK)   // 64
#define NTILES (CODEBOOK / BN) // 128
#define NSPLIT 2

// ---- scratch (device globals; no allocation allowed) ----
__device__ int   g_tok_idx[NTOK];
__device__ int   g_n_active;
__device__ float g_tsq[NTOK];          // t_sq / H per compacted slot
__device__ float g_csq[CODEBOOK];      // ||codebook row||^2
__device__ float g_partZ[NSPLIT][NTOK];
__device__ float g_partS[NSPLIT][NTOK];

// ============================================================
// 1) Compact image-token indices (deterministic, 1 block).
//    Probes whether token_type_ids buffer is int64 or int32.
// ============================================================
__global__ void compact_kernel(const int* __restrict__ tti)
{
    __shared__ int sodd;
    __shared__ int cnt[128];
    __shared__ int offs[128];
    int tid = threadIdx.x;
    if (tid == 0) sodd = 0;
    __syncthreads();

    // Probe first 4096 int2 (valid for both layouts). If data is int64,
    // all high words are 0; if int32, odd-index tokens include 1s.
    int acc = 0;
    for (int i = tid; i < 4096; i += 128) {
        int2 v = ((const int2*)tti)[i];
        acc |= v.y;
    }
    if (acc) atomicOr(&sodd, 1);
    __syncthreads();
    const int stride = sodd ? 1 : 2;   // int32 vs int64 (little-endian low word)

    const int base = tid * 64;
    int c = 0;
    for (int i = 0; i < 64; ++i)
        c += (tti[(base + i) * stride] == 1);
    cnt[tid] = c;
    __syncthreads();

    if (tid == 0) {
        int run = 0;
        for (int g = 0; g < 128; ++g) { offs[g] = run; run += cnt[g]; }
        g_n_active = run;
    }
    __syncthreads();

    int o = offs[tid];
    for (int i = 0; i < 64; ++i)
        if (tti[(base + i) * stride] == 1)
            g_tok_idx[o++] = base + i;
}

// ============================================================
// 2) c_sq[c] = ||codebook[c]||^2   (warp per row)
// ============================================================
__global__ void csq_kernel(const float* __restrict__ cb)
{
    int w    = blockIdx.x * 8 + (threadIdx.x >> 5);
    int lane = threadIdx.x & 31;
    const float* row = cb + (size_t)w * HIDDEN;
    float s = 0.f;
#pragma unroll
    for (int q = 0; q < 8; ++q) {
        float4 v = *(const float4*)(row + q * 128 + lane * 4);
        s += v.x * v.x + v.y * v.y + v.z * v.z + v.w * v.w;
    }
#pragma unroll
    for (int m = 16; m; m >>= 1) s += __shfl_xor_sync(0xffffffffu, s, m);
    if (lane == 0) g_csq[w] = s;
}

// ============================================================
// 3) t_sq per active token, pre-divided by H (warp per slot)
// ============================================================
__global__ void tsq_kernel(const float* __restrict__ tgt)
{
    int w    = blockIdx.x * 8 + (threadIdx.x >> 5);
    int lane = threadIdx.x & 31;
    if (w >= g_n_active) return;
    const float* row = tgt + (size_t)g_tok_idx[w] * HIDDEN;
    float s = 0.f;
#pragma unroll
    for (int q = 0; q < 8; ++q) {
        float4 v = *(const float4*)(row + q * 128 + lane * 4);
        s += v.x * v.x + v.y * v.y + v.z * v.z + v.w * v.w;
    }
#pragma unroll
    for (int m = 16; m; m >>= 1) s += __shfl_xor_sync(0xffffffffu, s, m);
    if (lane == 0) g_tsq[w] = s * (1.0f / HIDDEN);
}

// ============================================================
// 4) Main fused dual-GEMM + softmax-weighted reduction.
//    Block = 64 tokens x (64 codewords/iter), 256 threads,
//    4x4 register tile x 2 accumulator sets, double-buffered smem.
//    grid = (128, NSPLIT): y-splits the codebook range.
// ============================================================
__global__ __launch_bounds__(256, 2)
void tdl_main(const float* __restrict__ hs, const float* __restrict__ tgt,
              const float* __restrict__ cb, const float* __restrict__ W,
              const float* __restrict__ b)
{
    const int n_active = g_n_active;
    const int mtile = blockIdx.x;
    if (mtile * BM >= n_active) return;
    const int nhalf = blockIdx.y;

    __shared__ float sA1[2][BK][SMPAD];
    __shared__ float sA2[2][BK][SMPAD];
    __shared__ float sB1[2][BK][SMPAD];
    __shared__ float sB2[2][BK][SMPAD];

    const int tid  = threadIdx.x;
    const int tx   = tid & 15;          // codeword group (4 cols)
    const int ty   = tid >> 4;          // token group (4 rows)
    const int lrow = tid >> 2;          // 0..63 : row for A/B2 tile loads
    const int lk4  = (tid & 3) * 4;     // 0,4,8,12 : k offset for A/B2 loads
    const int bkr  = tid >> 4;          // 0..15 : k row for B1 (W) loads
    const int bnc4 = (tid & 15) * 4;    // col offset for B1 loads

    const int slot = mtile * BM + lrow;
    const int aidx = g_tok_idx[slot < n_active ? slot : 0];
    const float* pa1 = hs  + (size_t)aidx * HIDDEN + lk4;
    const float* pa2 = tgt + (size_t)aidx * HIDDEN + lk4;

    float Zacc[4] = {0.f, 0.f, 0.f, 0.f};
    float Sacc[4] = {0.f, 0.f, 0.f, 0.f};

    const int nt_beg = nhalf * (NTILES / NSPLIT);
    const int nt_end = nt_beg + (NTILES / NSPLIT);

    for (int nt = nt_beg; nt < nt_end; ++nt) {
        const int n0 = nt * BN;
        const float* pb2 = cb + (size_t)(n0 + lrow) * HIDDEN + lk4;
        const float* pb1 = W + (size_t)bkr * CODEBOOK + n0 + bnc4;

        float acc1[16], acc2[16];
#pragma unroll
        for (int i = 0; i < 16; ++i) { acc1[i] = 0.f; acc2[i] = 0.f; }

        // preload chunk 0
        float4 ra1 = *(const float4*)(pa1);
        float4 ra2 = *(const float4*)(pa2);
        float4 rb2 = *(const float4*)(pb2);
        float4 rb1 = *(const float4*)(pb1);
        {
            float* a1 = (float*)&ra1; float* a2 = (float*)&ra2; float* b2v = (float*)&rb2;
#pragma unroll
            for (int j = 0; j < 4; ++j) {
                sA1[0][lk4 + j][lrow] = a1[j];
                sA2[0][lk4 + j][lrow] = a2[j];
                sB2[0][lk4 + j][lrow] = b2v[j];
            }
            *(float4*)&sB1[0][bkr][bnc4] = rb1;
        }
        __syncthreads();

        int buf = 0;
        for (int kc = 0; kc < NCHUNK; ++kc) {
            const int k0n = (kc + 1) * BK;
            if (kc < NCHUNK - 1) {
                ra1 = *(const float4*)(pa1 + k0n);
                ra2 = *(const float4*)(pa2 + k0n);
                rb2 = *(const float4*)(pb2 + k0n);
                rb1 = *(const float4*)(pb1 + (size_t)k0n * CODEBOOK);
            }
            const float (*cA1)[SMPAD] = sA1[buf];
            const float (*cA2)[SMPAD] = sA2[buf];
            const float (*cB1)[SMPAD] = sB1[buf];
            const float (*cB2)[SMPAD] = sB2[buf];
#pragma unroll
            for (int k = 0; k < BK; ++k) {
                float a1[4], a2[4], b1[4], b2[4];
                *(float4*)a1 = *(const float4*)&cA1[k][ty * 4];
                *(float4*)a2 = *(const float4*)&cA2[k][ty * 4];
                *(float4*)b1 = *(const float4*)&cB1[k][tx * 4];
                *(float4*)b2 = *(const float4*)&cB2[k][tx * 4];
#pragma unroll
                for (int i = 0; i < 4; ++i)
#pragma unroll
                    for (int j = 0; j < 4; ++j) {
                        acc1[i * 4 + j] = fmaf(a1[i], b1[j], acc1[i * 4 + j]);
                        acc2[i * 4 + j] = fmaf(a2[i], b2[j], acc2[i * 4 + j]);
                    }
            }
            if (kc < NCHUNK - 1) {
                const int nb = buf ^ 1;
                float* a1 = (float*)&ra1; float* a2 = (float*)&ra2; float* b2v = (float*)&rb2;
#pragma unroll
                for (int j = 0; j < 4; ++j) {
                    sA1[nb][lk4 + j][lrow] = a1[j];
                    sA2[nb][lk4 + j][lrow] = a2[j];
                    sB2[nb][lk4 + j][lrow] = b2v[j];
                }
                *(float4*)&sB1[nb][bkr][bnc4] = rb1;
            }
            __syncthreads();
            buf ^= 1;
        }

        // epilogue: fold this 64x64 tile into running (Z, S)
        float bv[4], cq[4];
        *(float4*)bv = *(const float4*)(b + n0 + tx * 4);
        *(float4*)cq = *(const float4*)(&g_csq[n0 + tx * 4]);
#pragma unroll
        for (int i = 0; i < 4; ++i)
#pragma unroll
            for (int j = 0; j < 4; ++j) {
                const float l = acc1[i * 4 + j] + bv[j];
                const float e = __expf(l);
                const float v = fmaf(-2.f, acc2[i * 4 + j], cq[j]);
                Zacc[i] += e;
                Sacc[i] = fmaf(e, v, Sacc[i]);
            }
    }

    // reduce over the 16 tx lanes sharing each token (within warp halves)
#pragma unroll
    for (int i = 0; i < 4; ++i)
#pragma unroll
        for (int m = 8; m >= 1; m >>= 1) {
            Zacc[i] += __shfl_xor_sync(0xffffffffu, Zacc[i], m);
            Sacc[i] += __shfl_xor_sync(0xffffffffu, Sacc[i], m);
        }

    if (tx == 0) {
#pragma unroll
        for (int i = 0; i < 4; ++i) {
            const int s = mtile * BM + ty * 4 + i;
            if (s < n_active) {
                g_partZ[nhalf][s] = Zacc[i];
                g_partS[nhalf][s] = Sacc[i];
            }
        }
    }
}

// ============================================================
// 5) Final deterministic reduction to the scalar loss.
// ============================================================
__global__ void reduce_kernel(float* __restrict__ out)
{
    __shared__ float sm[256];
    const int tid = threadIdx.x;
    const int n = g_n_active;
    float s = 0.f;
    for (int i = tid; i < n; i += 256) {
        float Z = g_partZ[0][i] + g_partZ[1][i];
        float S = g_partS[0][i] + g_partS[1][i];
        s += g_tsq[i] + S / (Z * (float)HIDDEN);
    }
    sm[tid] = s;
    __syncthreads();
    for (int m = 128; m; m >>= 1) {
        if (tid < m) sm[tid] += sm[tid + m];
        __syncthreads();
    }
    if (tid == 0) out[0] = sm[0] * 0.1f;
}

// ============================================================
extern "C" void kernel_launch(void* const* d_in, const int* in_sizes, int n_in,
                              void* d_out, int out_size)
{
    (void)in_sizes; (void)n_in; (void)out_size;
    const float* hs  = (const float*)d_in[0];
    const int*   tti = (const int*)  d_in[1];
    const float* tgt = (const float*)d_in[2];
    const float* cb  = (const float*)d_in[3];
    const float* W   = (const float*)d_in[4];
    const float* b   = (const float*)d_in[5];
    float* out = (float*)d_out;

    compact_kernel<<<1, 128>>>(tti);
    csq_kernel<<<CODEBOOK / 8, 256>>>(cb);
    tsq_kernel<<<NTOK / 8, 256>>>(tgt);
    dim3 grid(NTOK / BM, NSPLIT);
    tdl_main<<<grid, 256>>>(hs, tgt, cb, W, b);
    reduce_kernel<<<1, 256>>>(out);
}

// round 8
// speedup vs baseline: 14.0595x; 14.0595x over previous
#include <cuda_runtime.h>
#include <cuda_bf16.h>
#include <cstdint>

#define HIDDEN   1024
#define CODEBOOK 8192
#define NTOK     8192
#define NSPLIT   8
#define BM       128
#define BN       128
#define BK       32
#define KCHUNKS  (HIDDEN / BK)                 // 32
#define NT_PER_BLOCK ((CODEBOOK / NSPLIT) / BN) // 8
#define STAGE_BYTES 32768
#define SMEM_TOTAL  (2 * STAGE_BYTES)

// ---------- device scratch (no runtime allocation allowed) ----------
__device__ int   g_tok_idx[NTOK];
__device__ int   g_n_active;
__device__ float g_tsq[NTOK];
__device__ float g_csq[CODEBOOK];
__device__ float g_partZ[NSPLIT][NTOK];
__device__ float g_partS[NSPLIT][NTOK];
__device__ __nv_bfloat16 g_A1[(size_t)NTOK * HIDDEN];      // hs, compacted
__device__ __nv_bfloat16 g_A2[(size_t)NTOK * HIDDEN];      // tgt, compacted
__device__ __nv_bfloat16 g_Wt[(size_t)CODEBOOK * HIDDEN];  // W transposed (K-major)
__device__ __nv_bfloat16 g_CB[(size_t)CODEBOOK * HIDDEN];  // codebook (K-major)

// ---------- portable PTX helpers (no 'a'-target features) ----------
#define CP_ASYNC16(saddr, gptr) \
    asm volatile("cp.async.cg.shared.global [%0], [%1], 16;" :: "r"(saddr), "l"(gptr))
#define CP_COMMIT()  asm volatile("cp.async.commit_group;" ::: "memory")
#define CP_WAIT1()   asm volatile("cp.async.wait_group 1;" ::: "memory")
#define CP_WAIT0()   asm volatile("cp.async.wait_group 0;" ::: "memory")

static __device__ __forceinline__ void ldsm4(uint32_t* r, uint32_t a) {
    asm volatile("ldmatrix.sync.aligned.m8n8.x4.shared.b16 {%0,%1,%2,%3}, [%4];"
                 : "=r"(r[0]), "=r"(r[1]), "=r"(r[2]), "=r"(r[3]) : "r"(a));
}
static __device__ __forceinline__ void mma16816(float* c, const uint32_t* a, const uint32_t* b) {
    asm volatile(
        "mma.sync.aligned.m16n8k16.row.col.f32.bf16.bf16.f32 "
        "{%0,%1,%2,%3}, {%4,%5,%6,%7}, {%8,%9}, {%0,%1,%2,%3};"
        : "+f"(c[0]), "+f"(c[1]), "+f"(c[2]), "+f"(c[3])
        : "r"(a[0]), "r"(a[1]), "r"(a[2]), "r"(a[3]), "r"(b[0]), "r"(b[1]));
}

// ============================================================
// 1) Compact image-token indices (deterministic, 1 block).
// ============================================================
__global__ void compact_kernel(const int* __restrict__ tti)
{
    __shared__ int sodd;
    __shared__ int cnt[128];
    __shared__ int offs[128];
    int tid = threadIdx.x;
    if (tid == 0) sodd = 0;
    __syncthreads();
    int acc = 0;
    for (int i = tid; i < 4096; i += 128) {
        int2 v = ((const int2*)tti)[i];
        acc |= v.y;
    }
    if (acc) atomicOr(&sodd, 1);
    __syncthreads();
    const int stride = sodd ? 1 : 2;   // int32 vs int64 layout probe

    const int base = tid * 64;
    int c = 0;
    for (int i = 0; i < 64; ++i) c += (tti[(base + i) * stride] == 1);
    cnt[tid] = c;
    __syncthreads();
    if (tid == 0) {
        int run = 0;
        for (int g = 0; g < 128; ++g) { offs[g] = run; run += cnt[g]; }
        g_n_active = run;
    }
    __syncthreads();
    int o = offs[tid];
    for (int i = 0; i < 64; ++i)
        if (tti[(base + i) * stride] == 1) g_tok_idx[o++] = base + i;
}

// ============================================================
// 2) c_sq / t_sq in exact fp32 (warp per row)
// ============================================================
__global__ void csq_kernel(const float* __restrict__ cb)
{
    int w = blockIdx.x * 8 + (threadIdx.x >> 5);
    int lane = threadIdx.x & 31;
    const float* row = cb + (size_t)w * HIDDEN;
    float s = 0.f;
#pragma unroll
    for (int q = 0; q < 8; ++q) {
        float4 v = *(const float4*)(row + q * 128 + lane * 4);
        s += v.x * v.x + v.y * v.y + v.z * v.z + v.w * v.w;
    }
#pragma unroll
    for (int m = 16; m; m >>= 1) s += __shfl_xor_sync(0xffffffffu, s, m);
    if (lane == 0) g_csq[w] = s;
}

__global__ void tsq_kernel(const float* __restrict__ tgt)
{
    int w = blockIdx.x * 8 + (threadIdx.x >> 5);
    int lane = threadIdx.x & 31;
    if (w >= g_n_active) return;
    const float* row = tgt + (size_t)g_tok_idx[w] * HIDDEN;
    float s = 0.f;
#pragma unroll
    for (int q = 0; q < 8; ++q) {
        float4 v = *(const float4*)(row + q * 128 + lane * 4);
        s += v.x * v.x + v.y * v.y + v.z * v.z + v.w * v.w;
    }
#pragma unroll
    for (int m = 16; m; m >>= 1) s += __shfl_xor_sync(0xffffffffu, s, m);
    if (lane == 0) g_tsq[w] = s * (1.0f / HIDDEN);
}

// ============================================================
// 3) bf16 packing kernels
// ============================================================
__global__ void pack_A_kernel(const float* __restrict__ hs, const float* __restrict__ tgt)
{
    int idx  = blockIdx.x * 256 + threadIdx.x;
    int slot = idx >> 8;
    int k4   = (idx & 255) * 4;
    __nv_bfloat162* o1 = (__nv_bfloat162*)(g_A1 + (size_t)slot * HIDDEN + k4);
    __nv_bfloat162* o2 = (__nv_bfloat162*)(g_A2 + (size_t)slot * HIDDEN + k4);
    if (slot < g_n_active) {
        size_t r = (size_t)g_tok_idx[slot] * HIDDEN + k4;
        float4 v1 = *(const float4*)(hs + r);
        float4 v2 = *(const float4*)(tgt + r);
        o1[0] = __floats2bfloat162_rn(v1.x, v1.y);
        o1[1] = __floats2bfloat162_rn(v1.z, v1.w);
        o2[0] = __floats2bfloat162_rn(v2.x, v2.y);
        o2[1] = __floats2bfloat162_rn(v2.z, v2.w);
    } else {
        __nv_bfloat162 z = __floats2bfloat162_rn(0.f, 0.f);
        o1[0] = z; o1[1] = z; o2[0] = z; o2[1] = z;
    }
}

__global__ void pack_CB_kernel(const float* __restrict__ cb)
{
    int idx = blockIdx.x * 256 + threadIdx.x;
    int c   = idx >> 8;
    int k4  = (idx & 255) * 4;
    float4 v = *(const float4*)(cb + (size_t)c * HIDDEN + k4);
    __nv_bfloat162* o = (__nv_bfloat162*)(g_CB + (size_t)c * HIDDEN + k4);
    o[0] = __floats2bfloat162_rn(v.x, v.y);
    o[1] = __floats2bfloat162_rn(v.z, v.w);
}

__global__ void pack_Wt_kernel(const float* __restrict__ W)
{
    __shared__ float t[32][33];
    int c0 = blockIdx.x * 32, h0 = blockIdx.y * 32;
    int tx = threadIdx.x, ty = threadIdx.y;       // (32, 8)
#pragma unroll
    for (int j = 0; j < 4; ++j)
        t[ty + 8 * j][tx] = W[(size_t)(h0 + ty + 8 * j) * CODEBOOK + c0 + tx];
    __syncthreads();
#pragma unroll
    for (int j = 0; j < 4; ++j)
        g_Wt[(size_t)(c0 + ty + 8 * j) * HIDDEN + h0 + tx] =
            __float2bfloat16_rn(t[tx][ty + 8 * j]);
}

// ============================================================
// 4) Fused dual-GEMM (HMMA bf16) + softmax-weighted reduce.
//    Block: 128 tokens x 128 codewords/iter, 8 warps (4M x 2N),
//    warp tile 32x64 per GEMM, BK=32, cp.async double buffer.
// ============================================================
__global__ void __launch_bounds__(256, 1)
tdl_hmma(const float* __restrict__ bb)
{
    extern __shared__ char smem[];
    const int tid = threadIdx.x;
    const int n_active = g_n_active;
    const int mtile = blockIdx.x;
    if (mtile * BM >= n_active) return;

    const int wid = tid >> 5, lane = tid & 31;
    const int wm = wid & 3, wn = wid >> 2;

    const __nv_bfloat16* pA1 = g_A1 + (size_t)mtile * BM * HIDDEN;
    const __nv_bfloat16* pA2 = g_A2 + (size_t)mtile * BM * HIDDEN;
    const int nbase = blockIdx.y * (CODEBOOK / NSPLIT);

    const uint32_t sbase = (uint32_t)__cvta_generic_to_shared(smem);

    // ---- cp.async slot precompute: thread -> (row, chunk) of a 128x32 tile ----
    // slot i (0..7): matrix = i>>1 (A1,A2,B1,B2), row = rowbase + (i&1)*64
    const int rowbase = tid >> 2;                  // 0..63
    const int ch      = tid & 3;                   // 16B chunk in 64B row
    const uint32_t sw = (uint32_t)((ch ^ ((rowbase >> 1) & 3)) << 4);
    const uint32_t soff = (uint32_t)rowbase * 64u + sw;     // smem off within matrix
    const size_t   goff = (size_t)rowbase * HIDDEN + ch * 8; // gmem elem off within matrix

    // ---- ldmatrix address precompute (XOR-swizzled 64B rows) ----
    uint32_t offA[2]; int xA[2];
#pragma unroll
    for (int mt = 0; mt < 2; ++mt) {
        int r = wm * 32 + mt * 16 + (lane & 7) + ((lane >> 3) & 1) * 8;
        offA[mt] = (uint32_t)r * 64u; xA[mt] = (r >> 1) & 3;
    }
    const int coffA = lane >> 4;                   // k-chunk select for A x4
    uint32_t offB[4]; int xB[4];
#pragma unroll
    for (int j = 0; j < 4; ++j) {
        int r = wn * 64 + j * 16 + (lane & 7) + ((lane >> 4) & 1) * 8;
        offB[j] = (uint32_t)r * 64u; xB[j] = (r >> 1) & 3;
    }
    const int coffB = (lane >> 3) & 1;             // k-chunk select for B x4

    float Zr[4], Sr[4];
#pragma unroll
    for (int r = 0; r < 4; ++r) { Zr[r] = 0.f; Sr[r] = 0.f; }

    for (int nt = 0; nt < NT_PER_BLOCK; ++nt) {
        const int n0 = nbase + nt * BN;
        const __nv_bfloat16* pB1 = g_Wt + (size_t)n0 * HIDDEN;
        const __nv_bfloat16* pB2 = g_CB + (size_t)n0 * HIDDEN;

        float acc1[64], acc2[64];
#pragma unroll
        for (int i = 0; i < 64; ++i) { acc1[i] = 0.f; acc2[i] = 0.f; }

        // issue one stage of copies (8 x 16B per thread)
        auto do_copy = [&](int stage, int kcc) {
            const uint32_t s0 = sbase + (uint32_t)stage * STAGE_BYTES;
            const size_t k0 = (size_t)kcc * BK;
#pragma unroll
            for (int i = 0; i < 8; ++i) {
                const __nv_bfloat16* mp = (i < 2) ? pA1 : (i < 4) ? pA2 : (i < 6) ? pB1 : pB2;
                const __nv_bfloat16* gp = mp + goff + ((i & 1) ? (size_t)64 * HIDDEN : 0) + k0;
                CP_ASYNC16(s0 + (uint32_t)(i >> 1) * 8192u + soff + ((i & 1) ? 4096u : 0u), gp);
            }
            CP_COMMIT();
        };

        do_copy(0, 0);
        do_copy(1, 1);

        for (int kc = 0; kc < KCHUNKS; ++kc) {
            CP_WAIT1();
            __syncthreads();
            const uint32_t sb = sbase + (uint32_t)(kc & 1) * STAGE_BYTES;
#pragma unroll
            for (int s = 0; s < 2; ++s) {
                uint32_t a1[2][4], a2[2][4];
#pragma unroll
                for (int mt = 0; mt < 2; ++mt) {
                    uint32_t off = offA[mt] + (uint32_t)(((2 * s + coffA) ^ xA[mt]) << 4);
                    ldsm4(a1[mt], sb + off);
                    ldsm4(a2[mt], sb + 8192u + off);
                }
#pragma unroll
                for (int j = 0; j < 4; ++j) {
                    uint32_t off = offB[j] + (uint32_t)(((2 * s + coffB) ^ xB[j]) << 4);
                    uint32_t b1[4], b2[4];
                    ldsm4(b1, sb + 16384u + off);
                    ldsm4(b2, sb + 24576u + off);
#pragma unroll
                    for (int mt = 0; mt < 2; ++mt) {
                        mma16816(&acc1[mt * 32 + (2 * j) * 4],     a1[mt], b1);
                        mma16816(&acc1[mt * 32 + (2 * j + 1) * 4], a1[mt], b1 + 2);
                        mma16816(&acc2[mt * 32 + (2 * j) * 4],     a2[mt], b2);
                        mma16816(&acc2[mt * 32 + (2 * j + 1) * 4], a2[mt], b2 + 2);
                    }
                }
            }
            __syncthreads();
            if (kc + 2 < KCHUNKS) do_copy(kc & 1, kc + 2);
            else CP_COMMIT();          // keep group counting consistent
        }
        CP_WAIT0();

        // ---- epilogue: fold 128x128 tile into per-token (Z, S) ----
#pragma unroll
        for (int ntl = 0; ntl < 8; ++ntl) {
            const int c0 = n0 + wn * 64 + ntl * 8 + (lane & 3) * 2;
            const float b0v = __ldg(bb + c0), b1v = __ldg(bb + c0 + 1);
            const float q0 = g_csq[c0], q1 = g_csq[c0 + 1];
#pragma unroll
            for (int mt = 0; mt < 2; ++mt) {
                const float* a1p = &acc1[mt * 32 + ntl * 4];
                const float* a2p = &acc2[mt * 32 + ntl * 4];
                float e0 = __expf(a1p[0] + b0v);
                float e1 = __expf(a1p[1] + b1v);
                Zr[mt * 2 + 0] += e0 + e1;
                Sr[mt * 2 + 0] += e0 * fmaf(-2.f, a2p[0], q0) + e1 * fmaf(-2.f, a2p[1], q1);
                float e2 = __expf(a1p[2] + b0v);
                float e3 = __expf(a1p[3] + b1v);
                Zr[mt * 2 + 1] += e2 + e3;
                Sr[mt * 2 + 1] += e2 * fmaf(-2.f, a2p[2], q0) + e3 * fmaf(-2.f, a2p[3], q1);
            }
        }
    }

    // ---- reduce across the 4 lanes sharing each row ----
#pragma unroll
    for (int r = 0; r < 4; ++r) {
        Zr[r] += __shfl_xor_sync(0xffffffffu, Zr[r], 1);
        Zr[r] += __shfl_xor_sync(0xffffffffu, Zr[r], 2);
        Sr[r] += __shfl_xor_sync(0xffffffffu, Sr[r], 1);
        Sr[r] += __shfl_xor_sync(0xffffffffu, Sr[r], 2);
    }
    __syncthreads();                    // smem stage area free for reuse
    float* zbuf = (float*)smem;         // [2][128]
    float* sbuf = zbuf + 256;           // [2][128]
    if ((lane & 3) == 0) {
        int gg = lane >> 2;
#pragma unroll
        for (int r = 0; r < 4; ++r) {
            int row = wm * 32 + (r >> 1) * 16 + (r & 1) * 8 + gg;
            zbuf[wn * 128 + row] = Zr[r];
            sbuf[wn * 128 + row] = Sr[r];
        }
    }
    __syncthreads();
    if (tid < 128) {
        int slot = mtile * BM + tid;
        if (slot < n_active) {
            g_partZ[blockIdx.y][slot] = zbuf[tid] + zbuf[128 + tid];
            g_partS[blockIdx.y][slot] = sbuf[tid] + sbuf[128 + tid];
        }
    }
}

// ============================================================
// 5) Final deterministic reduction.
// ============================================================
__global__ void reduce_kernel(float* __restrict__ out)
{
    __shared__ float sm[256];
    const int tid = threadIdx.x;
    const int n = g_n_active;
    float s = 0.f;
    for (int i = tid; i < n; i += 256) {
        float Z = 0.f, S = 0.f;
#pragma unroll
        for (int p = 0; p < NSPLIT; ++p) { Z += g_partZ[p][i]; S += g_partS[p][i]; }
        s += g_tsq[i] + S / (Z * (float)HIDDEN);
    }
    sm[tid] = s;
    __syncthreads();
    for (int m = 128; m; m >>= 1) {
        if (tid < m) sm[tid] += sm[tid + m];
        __syncthreads();
    }
    if (tid == 0) out[0] = sm[0] * 0.1f;
}

// ============================================================
extern "C" void kernel_launch(void* const* d_in, const int* in_sizes, int n_in,
                              void* d_out, int out_size)
{
    (void)in_sizes; (void)n_in; (void)out_size;
    const float* hs  = (const float*)d_in[0];
    const int*   tti = (const int*)  d_in[1];
    const float* tgt = (const float*)d_in[2];
    const float* cb  = (const float*)d_in[3];
    const float* W   = (const float*)d_in[4];
    const float* b   = (const float*)d_in[5];
    float* out = (float*)d_out;

    cudaFuncSetAttribute(tdl_hmma, cudaFuncAttributeMaxDynamicSharedMemorySize, SMEM_TOTAL);

    compact_kernel<<<1, 128>>>(tti);
    csq_kernel<<<CODEBOOK / 8, 256>>>(cb);
    tsq_kernel<<<NTOK / 8, 256>>>(tgt);
    pack_A_kernel<<<NTOK, 256>>>(hs, tgt);
    pack_CB_kernel<<<CODEBOOK, 256>>>(cb);
    pack_Wt_kernel<<<dim3(CODEBOOK / 32, HIDDEN / 32), dim3(32, 8)>>>(W);

    dim3 grid(NTOK / BM, NSPLIT);
    tdl_hmma<<<grid, 256, SMEM_TOTAL>>>(b);
    reduce_kernel<<<1, 256>>>(out);
}

// round 9
// speedup vs baseline: 14.2449x; 1.0132x over previous
#include <cuda_runtime.h>
#include <cuda_bf16.h>
#include <cstdint>

#define HIDDEN   1024
#define CODEBOOK 8192
#define NTOK     8192
#define NSPLIT   8
#define BM       128
#define BN       128
#define BK       32
#define KCHUNKS  (HIDDEN / BK)                  // 32
#define NT_PER_BLOCK ((CODEBOOK / NSPLIT) / BN) // 8
#define NGLOBAL  (NT_PER_BLOCK * KCHUNKS)       // 256 pipeline steps
#define STAGE_BYTES 32768
#define NSTAGE   3
#define SMEM_TOTAL  (NSTAGE * STAGE_BYTES)      // 96 KB

// ---------- device scratch (no runtime allocation allowed) ----------
__device__ int   g_tok_idx[NTOK];
__device__ int   g_n_active;
__device__ float g_tsq[NTOK];
__device__ float g_csq[CODEBOOK];
__device__ float g_partZ[NSPLIT][NTOK];
__device__ float g_partS[NSPLIT][NTOK];
__device__ __nv_bfloat16 g_A1[(size_t)NTOK * HIDDEN];      // hs, compacted
__device__ __nv_bfloat16 g_A2[(size_t)NTOK * HIDDEN];      // tgt, compacted
__device__ __nv_bfloat16 g_Wt[(size_t)CODEBOOK * HIDDEN];  // W transposed (K-major)
__device__ __nv_bfloat16 g_CB[(size_t)CODEBOOK * HIDDEN];  // codebook (K-major)

// ---------- portable PTX helpers (no 'a'-target features) ----------
#define CP_ASYNC16(saddr, gptr) \
    asm volatile("cp.async.cg.shared.global [%0], [%1], 16;" :: "r"(saddr), "l"(gptr))
#define CP_COMMIT()  asm volatile("cp.async.commit_group;" ::: "memory")
#define CP_WAIT1()   asm volatile("cp.async.wait_group 1;" ::: "memory")

static __device__ __forceinline__ void ldsm4(uint32_t* r, uint32_t a) {
    asm volatile("ldmatrix.sync.aligned.m8n8.x4.shared.b16 {%0,%1,%2,%3}, [%4];"
                 : "=r"(r[0]), "=r"(r[1]), "=r"(r[2]), "=r"(r[3]) : "r"(a));
}
static __device__ __forceinline__ void mma16816(float* c, const uint32_t* a, const uint32_t* b) {
    asm volatile(
        "mma.sync.aligned.m16n8k16.row.col.f32.bf16.bf16.f32 "
        "{%0,%1,%2,%3}, {%4,%5,%6,%7}, {%8,%9}, {%0,%1,%2,%3};"
        : "+f"(c[0]), "+f"(c[1]), "+f"(c[2]), "+f"(c[3])
        : "r"(a[0]), "r"(a[1]), "r"(a[2]), "r"(a[3]), "r"(b[0]), "r"(b[1]));
}

// ============================================================
// 1) Compact image-token indices (deterministic, 1 block, 1024 thr).
// ============================================================
__global__ void compact_kernel(const int* __restrict__ tti)
{
    __shared__ int sodd;
    __shared__ int wsum[32];
    const int tid = threadIdx.x;
    if (tid == 0) sodd = 0;
    __syncthreads();
    int acc = 0;
#pragma unroll
    for (int i = tid; i < 4096; i += 1024) acc |= ((const int2*)tti)[i].y;
    if (acc) atomicOr(&sodd, 1);
    __syncthreads();
    const int stride = sodd ? 1 : 2;   // int32 vs int64 layout probe

    const int base = tid * 8;
    int flags[8];
    int c = 0;
#pragma unroll
    for (int i = 0; i < 8; ++i) {
        flags[i] = (tti[(base + i) * stride] == 1);
        c += flags[i];
    }
    const int lane = tid & 31, w = tid >> 5;
    int p = c;
#pragma unroll
    for (int m = 1; m < 32; m <<= 1) {
        int t = __shfl_up_sync(0xffffffffu, p, m);
        if (lane >= m) p += t;
    }
    if (lane == 31) wsum[w] = p;
    __syncthreads();
    if (w == 0) {
        int v = wsum[lane];
#pragma unroll
        for (int m = 1; m < 32; m <<= 1) {
            int t = __shfl_up_sync(0xffffffffu, v, m);
            if (lane >= m) v += t;
        }
        wsum[lane] = v;
    }
    __syncthreads();
    const int wexcl = (w == 0) ? 0 : wsum[w - 1];
    int o = wexcl + p - c;
#pragma unroll
    for (int i = 0; i < 8; ++i)
        if (flags[i]) g_tok_idx[o++] = base + i;
    if (tid == 1023) g_n_active = wexcl + p;
}

// ============================================================
// 2) pack_A (+fused t_sq): block per compacted slot, 256 threads.
// ============================================================
__global__ void pack_A_kernel(const float* __restrict__ hs, const float* __restrict__ tgt)
{
    __shared__ float wred[8];
    const int slot = blockIdx.x;
    const int tid  = threadIdx.x;
    const int k4   = tid * 4;
    __nv_bfloat162* o1 = (__nv_bfloat162*)(g_A1 + (size_t)slot * HIDDEN + k4);
    __nv_bfloat162* o2 = (__nv_bfloat162*)(g_A2 + (size_t)slot * HIDDEN + k4);
    const int active = slot < g_n_active;
    float sq = 0.f;
    if (active) {
        size_t r = (size_t)g_tok_idx[slot] * HIDDEN + k4;
        float4 v1 = *(const float4*)(hs + r);
        float4 v2 = *(const float4*)(tgt + r);
        o1[0] = __floats2bfloat162_rn(v1.x, v1.y);
        o1[1] = __floats2bfloat162_rn(v1.z, v1.w);
        o2[0] = __floats2bfloat162_rn(v2.x, v2.y);
        o2[1] = __floats2bfloat162_rn(v2.z, v2.w);
        sq = v2.x * v2.x + v2.y * v2.y + v2.z * v2.z + v2.w * v2.w;
    } else {
        __nv_bfloat162 z = __floats2bfloat162_rn(0.f, 0.f);
        o1[0] = z; o1[1] = z; o2[0] = z; o2[1] = z;
        return;
    }
#pragma unroll
    for (int m = 16; m; m >>= 1) sq += __shfl_xor_sync(0xffffffffu, sq, m);
    if ((tid & 31) == 0) wred[tid >> 5] = sq;
    __syncthreads();
    if (tid == 0) {
        float s = 0.f;
#pragma unroll
        for (int i = 0; i < 8; ++i) s += wred[i];
        g_tsq[slot] = s * (1.0f / HIDDEN);
    }
}

// ============================================================
// 3) pack_CB (+fused c_sq): block per codebook row.
// ============================================================
__global__ void pack_CB_kernel(const float* __restrict__ cb)
{
    __shared__ float wred[8];
    const int c   = blockIdx.x;
    const int tid = threadIdx.x;
    const int k4  = tid * 4;
    float4 v = *(const float4*)(cb + (size_t)c * HIDDEN + k4);
    __nv_bfloat162* o = (__nv_bfloat162*)(g_CB + (size_t)c * HIDDEN + k4);
    o[0] = __floats2bfloat162_rn(v.x, v.y);
    o[1] = __floats2bfloat162_rn(v.z, v.w);
    float sq = v.x * v.x + v.y * v.y + v.z * v.z + v.w * v.w;
#pragma unroll
    for (int m = 16; m; m >>= 1) sq += __shfl_xor_sync(0xffffffffu, sq, m);
    if ((tid & 31) == 0) wred[tid >> 5] = sq;
    __syncthreads();
    if (tid == 0) {
        float s = 0.f;
#pragma unroll
        for (int i = 0; i < 8; ++i) s += wred[i];
        g_csq[c] = s;
    }
}

__global__ void pack_Wt_kernel(const float* __restrict__ W)
{
    __shared__ float t[32][33];
    int c0 = blockIdx.x * 32, h0 = blockIdx.y * 32;
    int tx = threadIdx.x, ty = threadIdx.y;       // (32, 8)
#pragma unroll
    for (int j = 0; j < 4; ++j)
        t[ty + 8 * j][tx] = W[(size_t)(h0 + ty + 8 * j) * CODEBOOK + c0 + tx];
    __syncthreads();
#pragma unroll
    for (int j = 0; j < 4; ++j)
        g_Wt[(size_t)(c0 + ty + 8 * j) * HIDDEN + h0 + tx] =
            __float2bfloat16_rn(t[tx][ty + 8 * j]);
}

// ============================================================
// 4) Fused dual-GEMM (HMMA bf16) + softmax-weighted reduce.
//    Flattened (nt,kc) pipeline: 3-stage cp.async, ONE sync/step,
//    epilogue overlaps next tile's loads.
// ============================================================
__global__ void __launch_bounds__(256, 1)
tdl_hmma(const float* __restrict__ bb)
{
    extern __shared__ char smem[];
    const int tid = threadIdx.x;
    const int n_active = g_n_active;
    const int mtile = blockIdx.x;
    if (mtile * BM >= n_active) return;

    const int wid = tid >> 5, lane = tid & 31;
    const int wm = wid & 3, wn = wid >> 2;

    const __nv_bfloat16* pA1 = g_A1 + (size_t)mtile * BM * HIDDEN;
    const __nv_bfloat16* pA2 = g_A2 + (size_t)mtile * BM * HIDDEN;
    const int nbase = blockIdx.y * (CODEBOOK / NSPLIT);

    const uint32_t sbase = (uint32_t)__cvta_generic_to_shared(smem);

    // ---- cp.async slot precompute: thread -> (row, chunk) of a 128x32 tile ----
    const int rowbase = tid >> 2;                   // 0..63
    const int ch      = tid & 3;                    // 16B chunk in 64B row
    const uint32_t sw = (uint32_t)((ch ^ ((rowbase >> 1) & 3)) << 4);
    const uint32_t soff = (uint32_t)rowbase * 64u + sw;
    const size_t   goff = (size_t)rowbase * HIDDEN + ch * 8;

    // ---- ldmatrix address precompute (XOR-swizzled 64B rows) ----
    uint32_t offA[2]; int xA[2];
#pragma unroll
    for (int mt = 0; mt < 2; ++mt) {
        int r = wm * 32 + mt * 16 + (lane & 7) + ((lane >> 3) & 1) * 8;
        offA[mt] = (uint32_t)r * 64u; xA[mt] = (r >> 1) & 3;
    }
    const int coffA = lane >> 4;
    uint32_t offB[4]; int xB[4];
#pragma unroll
    for (int j = 0; j < 4; ++j) {
        int r = wn * 64 + j * 16 + (lane & 7) + ((lane >> 4) & 1) * 8;
        offB[j] = (uint32_t)r * 64u; xB[j] = (r >> 1) & 3;
    }
    const int coffB = (lane >> 3) & 1;

    float Zr[4], Sr[4];
#pragma unroll
    for (int r = 0; r < 4; ++r) { Zr[r] = 0.f; Sr[r] = 0.f; }

    // issue one pipeline step's copies (8 x 16B per thread); ALWAYS commit
    auto issue = [&](int g) {
        if (g < NGLOBAL) {
            const int ntg = g >> 5, kcg = g & 31;
            const __nv_bfloat16* pB1 = g_Wt + (size_t)(nbase + ntg * BN) * HIDDEN;
            const __nv_bfloat16* pB2 = g_CB + (size_t)(nbase + ntg * BN) * HIDDEN;
            const uint32_t s0 = sbase + (uint32_t)(g % NSTAGE) * STAGE_BYTES;
            const size_t k0 = (size_t)kcg * BK;
#pragma unroll
            for (int i = 0; i < 8; ++i) {
                const __nv_bfloat16* mp = (i < 2) ? pA1 : (i < 4) ? pA2 : (i < 6) ? pB1 : pB2;
                const __nv_bfloat16* gp = mp + goff + ((i & 1) ? (size_t)64 * HIDDEN : 0) + k0;
                CP_ASYNC16(s0 + (uint32_t)(i >> 1) * 8192u + soff + ((i & 1) ? 4096u : 0u), gp);
            }
        }
        CP_COMMIT();
    };

    issue(0);
    issue(1);

    float acc1[64], acc2[64];

#pragma unroll 1
    for (int g = 0; g < NGLOBAL; ++g) {
        const int kc = g & 31;
        if (kc == 0) {
#pragma unroll
            for (int i = 0; i < 64; ++i) { acc1[i] = 0.f; acc2[i] = 0.f; }
        }
        CP_WAIT1();                 // group g complete (g+1 may be in flight)
        __syncthreads();
        issue(g + 2);               // writes stage (g+2)%3 == (g-1)%3, readers done

        const uint32_t sb = sbase + (uint32_t)(g % NSTAGE) * STAGE_BYTES;
#pragma unroll
        for (int s = 0; s < 2; ++s) {
            uint32_t a1[2][4], a2[2][4];
#pragma unroll
            for (int mt = 0; mt < 2; ++mt) {
                uint32_t off = offA[mt] + (uint32_t)(((2 * s + coffA) ^ xA[mt]) << 4);
                ldsm4(a1[mt], sb + off);
                ldsm4(a2[mt], sb + 8192u + off);
            }
#pragma unroll
            for (int j = 0; j < 4; ++j) {
                uint32_t off = offB[j] + (uint32_t)(((2 * s + coffB) ^ xB[j]) << 4);
                uint32_t b1[4], b2[4];
                ldsm4(b1, sb + 16384u + off);
                ldsm4(b2, sb + 24576u + off);
#pragma unroll
                for (int mt = 0; mt < 2; ++mt) {
                    mma16816(&acc1[mt * 32 + (2 * j) * 4],     a1[mt], b1);
                    mma16816(&acc1[mt * 32 + (2 * j + 1) * 4], a1[mt], b1 + 2);
                    mma16816(&acc2[mt * 32 + (2 * j) * 4],     a2[mt], b2);
                    mma16816(&acc2[mt * 32 + (2 * j + 1) * 4], a2[mt], b2 + 2);
                }
            }
        }

        if (kc == 31) {
            // epilogue overlaps the already-issued loads of the next tile
            const int n0 = nbase + (g >> 5) * BN;
#pragma unroll
            for (int ntl = 0; ntl < 8; ++ntl) {
                const int c0 = n0 + wn * 64 + ntl * 8 + (lane & 3) * 2;
                const float b0v = __ldg(bb + c0), b1v = __ldg(bb + c0 + 1);
                const float q0 = g_csq[c0], q1 = g_csq[c0 + 1];
#pragma unroll
                for (int mt = 0; mt < 2; ++mt) {
                    const float* a1p = &acc1[mt * 32 + ntl * 4];
                    const float* a2p = &acc2[mt * 32 + ntl * 4];
                    float e0 = __expf(a1p[0] + b0v);
                    float e1 = __expf(a1p[1] + b1v);
                    Zr[mt * 2 + 0] += e0 + e1;
                    Sr[mt * 2 + 0] += e0 * fmaf(-2.f, a2p[0], q0) + e1 * fmaf(-2.f, a2p[1], q1);
                    float e2 = __expf(a1p[2] + b0v);
                    float e3 = __expf(a1p[3] + b1v);
                    Zr[mt * 2 + 1] += e2 + e3;
                    Sr[mt * 2 + 1] += e2 * fmaf(-2.f, a2p[2], q0) + e3 * fmaf(-2.f, a2p[3], q1);
                }
            }
        }
    }

    // ---- reduce across the 4 lanes sharing each row ----
#pragma unroll
    for (int r = 0; r < 4; ++r) {
        Zr[r] += __shfl_xor_sync(0xffffffffu, Zr[r], 1);
        Zr[r] += __shfl_xor_sync(0xffffffffu, Zr[r], 2);
        Sr[r] += __shfl_xor_sync(0xffffffffu, Sr[r], 1);
        Sr[r] += __shfl_xor_sync(0xffffffffu, Sr[r], 2);
    }
    __syncthreads();                    // smem stage area free for reuse
    float* zbuf = (float*)smem;         // [2][128]
    float* sbuf = zbuf + 256;           // [2][128]
    if ((lane & 3) == 0) {
        int gg = lane >> 2;
#pragma unroll
        for (int r = 0; r < 4; ++r) {
            int row = wm * 32 + (r >> 1) * 16 + (r & 1) * 8 + gg;
            zbuf[wn * 128 + row] = Zr[r];
            sbuf[wn * 128 + row] = Sr[r];
        }
    }
    __syncthreads();
    if (tid < 128) {
        int slot = mtile * BM + tid;
        if (slot < n_active) {
            g_partZ[blockIdx.y][slot] = zbuf[tid] + zbuf[128 + tid];
            g_partS[blockIdx.y][slot] = sbuf[tid] + sbuf[128 + tid];
        }
    }
}

// ============================================================
// 5) Final deterministic reduction.
// ============================================================
__global__ void reduce_kernel(float* __restrict__ out)
{
    __shared__ float sm[256];
    const int tid = threadIdx.x;
    const int n = g_n_active;
    float s = 0.f;
    for (int i = tid; i < n; i += 256) {
        float Z = 0.f, S = 0.f;
#pragma unroll
        for (int p = 0; p < NSPLIT; ++p) { Z += g_partZ[p][i]; S += g_partS[p][i]; }
        s += g_tsq[i] + S / (Z * (float)HIDDEN);
    }
    sm[tid] = s;
    __syncthreads();
    for (int m = 128; m; m >>= 1) {
        if (tid < m) sm[tid] += sm[tid + m];
        __syncthreads();
    }
    if (tid == 0) out[0] = sm[0] * 0.1f;
}

// ============================================================
extern "C" void kernel_launch(void* const* d_in, const int* in_sizes, int n_in,
                              void* d_out, int out_size)
{
    (void)in_sizes; (void)n_in; (void)out_size;
    const float* hs  = (const float*)d_in[0];
    const int*   tti = (const int*)  d_in[1];
    const float* tgt = (const float*)d_in[2];
    const float* cb  = (const float*)d_in[3];
    const float* W   = (const float*)d_in[4];
    const float* b   = (const float*)d_in[5];
    float* out = (float*)d_out;

    cudaFuncSetAttribute(tdl_hmma, cudaFuncAttributeMaxDynamicSharedMemorySize, SMEM_TOTAL);

    compact_kernel<<<1, 1024>>>(tti);
    pack_A_kernel<<<NTOK, 256>>>(hs, tgt);
    pack_CB_kernel<<<CODEBOOK, 256>>>(cb);
    pack_Wt_kernel<<<dim3(CODEBOOK / 32, HIDDEN / 32), dim3(32, 8)>>>(W);

    dim3 grid(NTOK / BM, NSPLIT);
    tdl_hmma<<<grid, 256, SMEM_TOTAL>>>(b);
    reduce_kernel<<<1, 256>>>(out);
}